// round 1
// baseline (speedup 1.0000x reference)
#include <cuda_runtime.h>

#define EMBED 384
#define HEAD  64
#define BATCH 4
#define TSEQ  4096

// Scratch for projected q, k, v (4 MB each) — __device__ globals per alloc rules.
__device__ float g_q[BATCH * TSEQ * HEAD];
__device__ float g_k[BATCH * TSEQ * HEAD];
__device__ float g_v[BATCH * TSEQ * HEAD];

// ---------------------------------------------------------------------------
// Projection: [64 rows] x [3*64 cols] tile per block, K=384 in chunks of 32.
// x tile shared across Wq/Wk/Wv. 256 threads = 16x16, each 4 rows x (3x4) cols.
// ---------------------------------------------------------------------------
__global__ __launch_bounds__(256) void proj_kernel(
    const float* __restrict__ x,
    const float* __restrict__ Wq,
    const float* __restrict__ Wk,
    const float* __restrict__ Wv)
{
    __shared__ float AsT[32 * 64];   // [k][row]  (transposed x tile)
    __shared__ float Bs[32 * 192];   // [k][3*64] (Wq|Wk|Wv cols)

    const int tid  = threadIdx.x;
    const int tx   = tid & 15;       // col group
    const int ty   = tid >> 4;       // row group (0..15)
    const int row0 = blockIdx.x * 64;

    float acc[3][4][4];
#pragma unroll
    for (int m = 0; m < 3; m++)
#pragma unroll
        for (int i = 0; i < 4; i++)
#pragma unroll
            for (int j = 0; j < 4; j++) acc[m][i][j] = 0.f;

    for (int k0 = 0; k0 < EMBED; k0 += 32) {
        __syncthreads();
        // Load x tile transposed: rows fastest across lanes -> conflict-free STS.
        for (int ii = tid; ii < 512; ii += 256) {
            int r  = ii & 63;
            int k4 = ii >> 6;  // 0..7
            float4 v4 = *(const float4*)&x[(size_t)(row0 + r) * EMBED + k0 + k4 * 4];
            AsT[(k4 * 4 + 0) * 64 + r] = v4.x;
            AsT[(k4 * 4 + 1) * 64 + r] = v4.y;
            AsT[(k4 * 4 + 2) * 64 + r] = v4.z;
            AsT[(k4 * 4 + 3) * 64 + r] = v4.w;
        }
        // Load the three W tiles (coalesced float4, conflict-free STS).
#pragma unroll
        for (int m = 0; m < 3; m++) {
            const float* W = (m == 0) ? Wq : ((m == 1) ? Wk : Wv);
            for (int ii = tid; ii < 512; ii += 256) {
                int c4 = ii & 15;
                int kr = ii >> 4;  // 0..31
                *(float4*)&Bs[kr * 192 + m * 64 + c4 * 4] =
                    *(const float4*)&W[(size_t)(k0 + kr) * HEAD + c4 * 4];
            }
        }
        __syncthreads();

#pragma unroll 4
        for (int k = 0; k < 32; k++) {
            float4 a4 = *(const float4*)&AsT[k * 64 + ty * 4];
            float a[4] = {a4.x, a4.y, a4.z, a4.w};
#pragma unroll
            for (int m = 0; m < 3; m++) {
                float4 b4 = *(const float4*)&Bs[k * 192 + m * 64 + tx * 4];
                float bb[4] = {b4.x, b4.y, b4.z, b4.w};
#pragma unroll
                for (int i = 0; i < 4; i++)
#pragma unroll
                    for (int j = 0; j < 4; j++) acc[m][i][j] += a[i] * bb[j];
            }
        }
    }

#pragma unroll
    for (int m = 0; m < 3; m++) {
        float* g = (m == 0) ? g_q : ((m == 1) ? g_k : g_v);
#pragma unroll
        for (int i = 0; i < 4; i++) {
            float4 v4 = make_float4(acc[m][i][0], acc[m][i][1], acc[m][i][2], acc[m][i][3]);
            *(float4*)&g[(size_t)(row0 + ty * 4 + i) * HEAD + tx * 4] = v4;
        }
    }
}

// ---------------------------------------------------------------------------
// Flash attention, causal. BM=BN=64, D=64. 128 threads (16 tx x 8 ty),
// each thread owns an 8x4 score tile and 8x4 output tile.
// Smem layouts transposed ([d][n]) so every LDS.128 is lane-consecutive
// or broadcast -> zero bank conflicts.
// ---------------------------------------------------------------------------
__global__ __launch_bounds__(128) void attn_kernel(float* __restrict__ out)
{
    extern __shared__ float sm[];
    float* QsT = sm;                 // [d][r]  64x64
    float* KsT = sm + 64 * 64;       // [d][n]  64x64
    float* Vs  = sm + 2 * 64 * 64;   // [n][d]  64x64
    float* Ps  = sm + 3 * 64 * 64;   // [r][n]  64x64

    const int b   = blockIdx.y;
    const int qt  = (int)gridDim.x - 1 - (int)blockIdx.x;  // big blocks first
    const int tid = threadIdx.x;
    const int tx  = tid & 15;
    const int ty  = tid >> 4;        // 0..7
    const int r0  = ty * 8;
    const int c0  = tx * 4;

    const float* Qb = g_q + ((size_t)b * TSEQ + (size_t)qt * 64) * HEAD;
    const float* Kb = g_k + (size_t)b * TSEQ * HEAD;
    const float* Vb = g_v + (size_t)b * TSEQ * HEAD;

    const float scale = 0.125f;  // HEAD^-0.5, folded into Q

    // Load Q tile transposed + pre-scaled.
    for (int ii = tid; ii < 1024; ii += 128) {
        int r  = ii & 63;
        int d4 = ii >> 6;  // 0..15
        float4 v4 = *(const float4*)&Qb[r * HEAD + d4 * 4];
        QsT[(d4 * 4 + 0) * 64 + r] = v4.x * scale;
        QsT[(d4 * 4 + 1) * 64 + r] = v4.y * scale;
        QsT[(d4 * 4 + 2) * 64 + r] = v4.z * scale;
        QsT[(d4 * 4 + 3) * 64 + r] = v4.w * scale;
    }

    float o[8][4], m[8], l[8];
#pragma unroll
    for (int i = 0; i < 8; i++) {
        m[i] = -1e30f;
        l[i] = 0.f;
#pragma unroll
        for (int j = 0; j < 4; j++) o[i][j] = 0.f;
    }

    for (int kt = 0; kt <= qt; kt++) {
        __syncthreads();  // prev iter done reading KsT/Vs/Ps (also covers Q store)
        const float* Kt = Kb + (size_t)kt * 64 * HEAD;
        const float* Vt = Vb + (size_t)kt * 64 * HEAD;
        for (int ii = tid; ii < 1024; ii += 128) {
            int r  = ii & 63;
            int d4 = ii >> 6;
            float4 v4 = *(const float4*)&Kt[r * HEAD + d4 * 4];
            KsT[(d4 * 4 + 0) * 64 + r] = v4.x;
            KsT[(d4 * 4 + 1) * 64 + r] = v4.y;
            KsT[(d4 * 4 + 2) * 64 + r] = v4.z;
            KsT[(d4 * 4 + 3) * 64 + r] = v4.w;
        }
        for (int ii = tid; ii < 1024; ii += 128) {
            int d4 = ii & 15;
            int r  = ii >> 4;
            *(float4*)&Vs[r * 64 + d4 * 4] = *(const float4*)&Vt[r * HEAD + d4 * 4];
        }
        __syncthreads();

        // S = Q @ K^T (scaled). 3 LDS.128 + 32 FMA per d.
        float s[8][4];
#pragma unroll
        for (int i = 0; i < 8; i++)
#pragma unroll
            for (int j = 0; j < 4; j++) s[i][j] = 0.f;

#pragma unroll 4
        for (int d = 0; d < 64; d++) {
            float4 q0 = *(const float4*)&QsT[d * 64 + r0];
            float4 q1 = *(const float4*)&QsT[d * 64 + r0 + 4];
            float4 kv = *(const float4*)&KsT[d * 64 + c0];
            float qq[8] = {q0.x, q0.y, q0.z, q0.w, q1.x, q1.y, q1.z, q1.w};
            float kk[4] = {kv.x, kv.y, kv.z, kv.w};
#pragma unroll
            for (int i = 0; i < 8; i++)
#pragma unroll
                for (int j = 0; j < 4; j++) s[i][j] += qq[i] * kk[j];
        }

        if (kt == qt) {  // diagonal tile: causal mask (local indices, qt==kt)
#pragma unroll
            for (int i = 0; i < 8; i++)
#pragma unroll
                for (int j = 0; j < 4; j++)
                    if (c0 + j > r0 + i) s[i][j] = -1e30f;
        }

        // Online softmax update. Row stats reduced across the 16 tx lanes.
#pragma unroll
        for (int i = 0; i < 8; i++) {
            float mx = fmaxf(fmaxf(s[i][0], s[i][1]), fmaxf(s[i][2], s[i][3]));
            mx = fmaxf(mx, __shfl_xor_sync(0xffffffffu, mx, 1));
            mx = fmaxf(mx, __shfl_xor_sync(0xffffffffu, mx, 2));
            mx = fmaxf(mx, __shfl_xor_sync(0xffffffffu, mx, 4));
            mx = fmaxf(mx, __shfl_xor_sync(0xffffffffu, mx, 8));
            float mn    = fmaxf(m[i], mx);
            float alpha = __expf(m[i] - mn);
            float sum   = 0.f;
#pragma unroll
            for (int j = 0; j < 4; j++) {
                float p = __expf(s[i][j] - mn);
                s[i][j] = p;
                sum += p;
            }
            sum += __shfl_xor_sync(0xffffffffu, sum, 1);
            sum += __shfl_xor_sync(0xffffffffu, sum, 2);
            sum += __shfl_xor_sync(0xffffffffu, sum, 4);
            sum += __shfl_xor_sync(0xffffffffu, sum, 8);
            l[i] = l[i] * alpha + sum;
            m[i] = mn;
#pragma unroll
            for (int j = 0; j < 4; j++) o[i][j] *= alpha;
        }

        // P to smem (lane-consecutive float4 stores, conflict-free).
#pragma unroll
        for (int i = 0; i < 8; i++)
            *(float4*)&Ps[(r0 + i) * 64 + c0] = make_float4(s[i][0], s[i][1], s[i][2], s[i][3]);
        __syncthreads();

        // O += P @ V. 12 LDS.128 + 128 FMA per n4 step.
#pragma unroll 2
        for (int n4 = 0; n4 < 16; n4++) {
            float4 v0 = *(const float4*)&Vs[(n4 * 4 + 0) * 64 + c0];
            float4 v1 = *(const float4*)&Vs[(n4 * 4 + 1) * 64 + c0];
            float4 v2 = *(const float4*)&Vs[(n4 * 4 + 2) * 64 + c0];
            float4 v3 = *(const float4*)&Vs[(n4 * 4 + 3) * 64 + c0];
#pragma unroll
            for (int i = 0; i < 8; i++) {
                float4 p4 = *(const float4*)&Ps[(r0 + i) * 64 + n4 * 4];
                o[i][0] += p4.x * v0.x + p4.y * v1.x + p4.z * v2.x + p4.w * v3.x;
                o[i][1] += p4.x * v0.y + p4.y * v1.y + p4.z * v2.y + p4.w * v3.y;
                o[i][2] += p4.x * v0.z + p4.y * v1.z + p4.z * v2.z + p4.w * v3.z;
                o[i][3] += p4.x * v0.w + p4.y * v1.w + p4.z * v2.w + p4.w * v3.w;
            }
        }
    }

    // Epilogue: normalize and store.
    float* Ob = out + ((size_t)b * TSEQ + (size_t)qt * 64) * HEAD;
#pragma unroll
    for (int i = 0; i < 8; i++) {
        float inv = 1.0f / l[i];
        *(float4*)&Ob[(r0 + i) * HEAD + c0] =
            make_float4(o[i][0] * inv, o[i][1] * inv, o[i][2] * inv, o[i][3] * inv);
    }
}

// ---------------------------------------------------------------------------
extern "C" void kernel_launch(void* const* d_in, const int* in_sizes, int n_in,
                              void* d_out, int out_size)
{
    (void)in_sizes; (void)n_in; (void)out_size;
    const float* x  = (const float*)d_in[0];
    const float* Wq = (const float*)d_in[1];
    const float* Wk = (const float*)d_in[2];
    const float* Wv = (const float*)d_in[3];
    float* out = (float*)d_out;

    proj_kernel<<<(BATCH * TSEQ) / 64, 256>>>(x, Wq, Wk, Wv);

    const int smem_bytes = 4 * 64 * 64 * (int)sizeof(float);  // 64 KB
    cudaFuncSetAttribute(attn_kernel, cudaFuncAttributeMaxDynamicSharedMemorySize, smem_bytes);
    dim3 grid(TSEQ / 64, BATCH);
    attn_kernel<<<grid, 128, smem_bytes>>>(out);
}

// round 2
// speedup vs baseline: 1.6923x; 1.6923x over previous
#include <cuda_runtime.h>

#define EMBED 384
#define HEAD  64
#define BATCH 4
#define TSEQ  4096
#define NQT   64          // 64-row q tiles per batch
#define CHUNK 8           // kv tiles per work unit
#define UNITS_PER_B 288   // sum over bands: 8*(1+2+...+8)
#define MAXC  8           // max chunks per q tile

// Scratch (__device__ globals per alloc rules).
__device__ float g_q[BATCH * TSEQ * HEAD];
__device__ float g_k[BATCH * TSEQ * HEAD];
__device__ float g_v[BATCH * TSEQ * HEAD];
__device__ float g_opart[BATCH * NQT * MAXC * 64 * 64];   // unnormalized partial O
__device__ float g_mpart[BATCH * NQT * MAXC * 64];
__device__ float g_lpart[BATCH * NQT * MAXC * 64];

// ---- packed f32x2 helpers (Blackwell FFMA2 path, PTX-only) -----------------
__device__ __forceinline__ unsigned long long pk2(float a, float b) {
    unsigned long long r;
    asm("mov.b64 %0, {%1, %2};" : "=l"(r) : "f"(a), "f"(b));
    return r;
}
__device__ __forceinline__ float2 upk2(unsigned long long a) {
    float x, y;
    asm("mov.b64 {%0, %1}, %2;" : "=f"(x), "=f"(y) : "l"(a));
    return make_float2(x, y);
}
__device__ __forceinline__ unsigned long long ffma2(
    unsigned long long a, unsigned long long b, unsigned long long c) {
    unsigned long long d;
    asm("fma.rn.f32x2 %0, %1, %2, %3;" : "=l"(d) : "l"(a), "l"(b), "l"(c));
    return d;
}
__device__ __forceinline__ unsigned long long fmul2(
    unsigned long long a, unsigned long long b) {
    unsigned long long d;
    asm("mul.rn.f32x2 %0, %1, %2;" : "=l"(d) : "l"(a), "l"(b));
    return d;
}

// ---------------------------------------------------------------------------
// Projection: 64 rows x (3*64) cols per block, K chunks of 32, f32x2 FMAs.
// ---------------------------------------------------------------------------
__global__ __launch_bounds__(256) void proj_kernel(
    const float* __restrict__ x,
    const float* __restrict__ Wq,
    const float* __restrict__ Wk,
    const float* __restrict__ Wv)
{
    __shared__ float AsT[32 * 64];   // [k][row]
    __shared__ float Bs[32 * 192];   // [k][3*64]

    const int tid  = threadIdx.x;
    const int tx   = tid & 15;
    const int ty   = tid >> 4;
    const int row0 = blockIdx.x * 64;

    unsigned long long acc2[3][4][2];
#pragma unroll
    for (int m = 0; m < 3; m++)
#pragma unroll
        for (int i = 0; i < 4; i++) { acc2[m][i][0] = 0ull; acc2[m][i][1] = 0ull; }

    for (int k0 = 0; k0 < EMBED; k0 += 32) {
        __syncthreads();
        for (int ii = tid; ii < 512; ii += 256) {
            int r  = ii & 63;
            int k4 = ii >> 6;
            float4 v4 = *(const float4*)&x[(size_t)(row0 + r) * EMBED + k0 + k4 * 4];
            AsT[(k4 * 4 + 0) * 64 + r] = v4.x;
            AsT[(k4 * 4 + 1) * 64 + r] = v4.y;
            AsT[(k4 * 4 + 2) * 64 + r] = v4.z;
            AsT[(k4 * 4 + 3) * 64 + r] = v4.w;
        }
#pragma unroll
        for (int m = 0; m < 3; m++) {
            const float* W = (m == 0) ? Wq : ((m == 1) ? Wk : Wv);
            for (int ii = tid; ii < 512; ii += 256) {
                int c4 = ii & 15;
                int kr = ii >> 4;
                *(float4*)&Bs[kr * 192 + m * 64 + c4 * 4] =
                    *(const float4*)&W[(size_t)(k0 + kr) * HEAD + c4 * 4];
            }
        }
        __syncthreads();

#pragma unroll 4
        for (int k = 0; k < 32; k++) {
            float4 a4 = *(const float4*)&AsT[k * 64 + ty * 4];
            unsigned long long ai2[4] = {pk2(a4.x, a4.x), pk2(a4.y, a4.y),
                                         pk2(a4.z, a4.z), pk2(a4.w, a4.w)};
#pragma unroll
            for (int m = 0; m < 3; m++) {
                float4 b4 = *(const float4*)&Bs[k * 192 + m * 64 + tx * 4];
                unsigned long long b01 = pk2(b4.x, b4.y);
                unsigned long long b23 = pk2(b4.z, b4.w);
#pragma unroll
                for (int i = 0; i < 4; i++) {
                    acc2[m][i][0] = ffma2(ai2[i], b01, acc2[m][i][0]);
                    acc2[m][i][1] = ffma2(ai2[i], b23, acc2[m][i][1]);
                }
            }
        }
    }

#pragma unroll
    for (int m = 0; m < 3; m++) {
        float* g = (m == 0) ? g_q : ((m == 1) ? g_k : g_v);
#pragma unroll
        for (int i = 0; i < 4; i++) {
            float2 lo = upk2(acc2[m][i][0]);
            float2 hi = upk2(acc2[m][i][1]);
            *(float4*)&g[(size_t)(row0 + ty * 4 + i) * HEAD + tx * 4] =
                make_float4(lo.x, lo.y, hi.x, hi.y);
        }
    }
}

// ---------------------------------------------------------------------------
// Flash attention, split-KV. One CTA = (batch, q-tile, chunk of <=8 kv tiles).
// 128 threads (16 tx x 8 ty), 8x4 per-thread tile, f32x2 packed FMAs.
// ---------------------------------------------------------------------------
__global__ __launch_bounds__(128) void attn_kernel(float* __restrict__ out)
{
    extern __shared__ float sm[];
    float* QsT = sm;                 // [d][r]  64x64
    float* KsT = sm + 64 * 64;       // [d][n]  64x64
    float* Vs  = sm + 2 * 64 * 64;   // [n][d]  64x64
    float* Ps  = sm + 3 * 64 * 64;   // [r][n]  64x64

    const int b   = blockIdx.y;
    const int uid = UNITS_PER_B - 1 - (int)blockIdx.x;  // heavy units first

    // Decode uid -> (q tile, chunk). Band bd covers q in [8*bd, 8*bd+7],
    // each q there has bd+1 chunks.
    int rem = uid, band = 0;
    while (rem >= 8 * (band + 1)) { rem -= 8 * (band + 1); band++; }
    const int q  = band * 8 + rem / (band + 1);
    const int c  = rem % (band + 1);
    const int nc = (q >> 3) + 1;     // ceil((q+1)/8) == q/8 + 1

    const int kt0 = c * CHUNK;
    const int kt1 = min(kt0 + CHUNK - 1, q);

    const int tid = threadIdx.x;
    const int tx  = tid & 15;
    const int ty  = tid >> 4;
    const int r0  = ty * 8;
    const int c0  = tx * 4;

    const float* Qb = g_q + ((size_t)b * TSEQ + (size_t)q * 64) * HEAD;
    const float* Kb = g_k + (size_t)b * TSEQ * HEAD;
    const float* Vb = g_v + (size_t)b * TSEQ * HEAD;

    const float scale = 0.125f;  // HEAD^-0.5 folded into Q

    for (int ii = tid; ii < 1024; ii += 128) {
        int r  = ii & 63;
        int d4 = ii >> 6;
        float4 v4 = *(const float4*)&Qb[r * HEAD + d4 * 4];
        QsT[(d4 * 4 + 0) * 64 + r] = v4.x * scale;
        QsT[(d4 * 4 + 1) * 64 + r] = v4.y * scale;
        QsT[(d4 * 4 + 2) * 64 + r] = v4.z * scale;
        QsT[(d4 * 4 + 3) * 64 + r] = v4.w * scale;
    }

    unsigned long long o2[8][2];
    float m[8], l[8];
#pragma unroll
    for (int i = 0; i < 8; i++) {
        m[i] = -1e30f; l[i] = 0.f; o2[i][0] = 0ull; o2[i][1] = 0ull;
    }

    for (int kt = kt0; kt <= kt1; kt++) {
        __syncthreads();
        const float* Kt = Kb + (size_t)kt * 64 * HEAD;
        const float* Vt = Vb + (size_t)kt * 64 * HEAD;
        for (int ii = tid; ii < 1024; ii += 128) {
            int r  = ii & 63;
            int d4 = ii >> 6;
            float4 v4 = *(const float4*)&Kt[r * HEAD + d4 * 4];
            KsT[(d4 * 4 + 0) * 64 + r] = v4.x;
            KsT[(d4 * 4 + 1) * 64 + r] = v4.y;
            KsT[(d4 * 4 + 2) * 64 + r] = v4.z;
            KsT[(d4 * 4 + 3) * 64 + r] = v4.w;
        }
        for (int ii = tid; ii < 1024; ii += 128) {
            int d4 = ii & 15;
            int r  = ii >> 4;
            *(float4*)&Vs[r * 64 + d4 * 4] = *(const float4*)&Vt[r * HEAD + d4 * 4];
        }
        __syncthreads();

        // S = Q @ K^T, packed col-pairs.
        unsigned long long s2[8][2];
#pragma unroll
        for (int i = 0; i < 8; i++) { s2[i][0] = 0ull; s2[i][1] = 0ull; }

#pragma unroll 4
        for (int d = 0; d < 64; d++) {
            float4 q0 = *(const float4*)&QsT[d * 64 + r0];
            float4 q1 = *(const float4*)&QsT[d * 64 + r0 + 4];
            float4 kv = *(const float4*)&KsT[d * 64 + c0];
            unsigned long long k01 = pk2(kv.x, kv.y);
            unsigned long long k23 = pk2(kv.z, kv.w);
            float qq[8] = {q0.x, q0.y, q0.z, q0.w, q1.x, q1.y, q1.z, q1.w};
#pragma unroll
            for (int i = 0; i < 8; i++) {
                unsigned long long qi2 = pk2(qq[i], qq[i]);
                s2[i][0] = ffma2(qi2, k01, s2[i][0]);
                s2[i][1] = ffma2(qi2, k23, s2[i][1]);
            }
        }

        float s[8][4];
#pragma unroll
        for (int i = 0; i < 8; i++) {
            float2 a = upk2(s2[i][0]);
            float2 bb = upk2(s2[i][1]);
            s[i][0] = a.x; s[i][1] = a.y; s[i][2] = bb.x; s[i][3] = bb.y;
        }

        if (kt == q) {  // diagonal tile: causal mask
#pragma unroll
            for (int i = 0; i < 8; i++)
#pragma unroll
                for (int j = 0; j < 4; j++)
                    if (c0 + j > r0 + i) s[i][j] = -1e30f;
        }

        // Online softmax update.
#pragma unroll
        for (int i = 0; i < 8; i++) {
            float mx = fmaxf(fmaxf(s[i][0], s[i][1]), fmaxf(s[i][2], s[i][3]));
            mx = fmaxf(mx, __shfl_xor_sync(0xffffffffu, mx, 1));
            mx = fmaxf(mx, __shfl_xor_sync(0xffffffffu, mx, 2));
            mx = fmaxf(mx, __shfl_xor_sync(0xffffffffu, mx, 4));
            mx = fmaxf(mx, __shfl_xor_sync(0xffffffffu, mx, 8));
            float mn    = fmaxf(m[i], mx);
            float alpha = __expf(m[i] - mn);
            float sum   = 0.f;
#pragma unroll
            for (int j = 0; j < 4; j++) {
                float p = __expf(s[i][j] - mn);
                s[i][j] = p;
                sum += p;
            }
            sum += __shfl_xor_sync(0xffffffffu, sum, 1);
            sum += __shfl_xor_sync(0xffffffffu, sum, 2);
            sum += __shfl_xor_sync(0xffffffffu, sum, 4);
            sum += __shfl_xor_sync(0xffffffffu, sum, 8);
            l[i] = l[i] * alpha + sum;
            m[i] = mn;
            unsigned long long a2 = pk2(alpha, alpha);
            o2[i][0] = fmul2(o2[i][0], a2);
            o2[i][1] = fmul2(o2[i][1], a2);
        }

#pragma unroll
        for (int i = 0; i < 8; i++)
            *(float4*)&Ps[(r0 + i) * 64 + c0] =
                make_float4(s[i][0], s[i][1], s[i][2], s[i][3]);
        __syncthreads();

        // O += P @ V, packed col-pairs.
#pragma unroll 2
        for (int n4 = 0; n4 < 16; n4++) {
            float4 v0 = *(const float4*)&Vs[(n4 * 4 + 0) * 64 + c0];
            float4 v1 = *(const float4*)&Vs[(n4 * 4 + 1) * 64 + c0];
            float4 v2 = *(const float4*)&Vs[(n4 * 4 + 2) * 64 + c0];
            float4 v3 = *(const float4*)&Vs[(n4 * 4 + 3) * 64 + c0];
            unsigned long long v0a = pk2(v0.x, v0.y), v0b = pk2(v0.z, v0.w);
            unsigned long long v1a = pk2(v1.x, v1.y), v1b = pk2(v1.z, v1.w);
            unsigned long long v2a = pk2(v2.x, v2.y), v2b = pk2(v2.z, v2.w);
            unsigned long long v3a = pk2(v3.x, v3.y), v3b = pk2(v3.z, v3.w);
#pragma unroll
            for (int i = 0; i < 8; i++) {
                float4 p4 = *(const float4*)&Ps[(r0 + i) * 64 + n4 * 4];
                unsigned long long px = pk2(p4.x, p4.x), py = pk2(p4.y, p4.y);
                unsigned long long pz = pk2(p4.z, p4.z), pw = pk2(p4.w, p4.w);
                unsigned long long oa = o2[i][0], ob = o2[i][1];
                oa = ffma2(px, v0a, oa); ob = ffma2(px, v0b, ob);
                oa = ffma2(py, v1a, oa); ob = ffma2(py, v1b, ob);
                oa = ffma2(pz, v2a, oa); ob = ffma2(pz, v2b, ob);
                oa = ffma2(pw, v3a, oa); ob = ffma2(pw, v3b, ob);
                o2[i][0] = oa; o2[i][1] = ob;
            }
        }
    }

    if (nc == 1) {
        // Single chunk covers everything: normalize and write final output.
        float* Ob = out + ((size_t)b * TSEQ + (size_t)q * 64) * HEAD;
#pragma unroll
        for (int i = 0; i < 8; i++) {
            float inv = 1.0f / l[i];
            float2 a = upk2(o2[i][0]);
            float2 bb = upk2(o2[i][1]);
            *(float4*)&Ob[(r0 + i) * HEAD + c0] =
                make_float4(a.x * inv, a.y * inv, bb.x * inv, bb.y * inv);
        }
    } else {
        // Write unnormalized partial + stats for the combine kernel.
        float* gp = g_opart + (((size_t)(b * NQT + q) * MAXC + c) * 4096);
#pragma unroll
        for (int i = 0; i < 8; i++) {
            float2 a = upk2(o2[i][0]);
            float2 bb = upk2(o2[i][1]);
            *(float4*)&gp[(r0 + i) * 64 + c0] = make_float4(a.x, a.y, bb.x, bb.y);
        }
        if (tx == 0) {
            float* gm = g_mpart + ((size_t)(b * NQT + q) * MAXC + c) * 64;
            float* gl = g_lpart + ((size_t)(b * NQT + q) * MAXC + c) * 64;
#pragma unroll
            for (int i = 0; i < 8; i++) { gm[r0 + i] = m[i]; gl[r0 + i] = l[i]; }
        }
    }
}

// ---------------------------------------------------------------------------
// Combine split-KV partials for q tiles with nc >= 2 (q >= 8).
// Grid: (NQT-8, BATCH), 128 threads. Thread handles one row-half (32 cols).
// ---------------------------------------------------------------------------
__global__ __launch_bounds__(128) void combine_kernel(float* __restrict__ out)
{
    const int q  = 8 + blockIdx.x;
    const int b  = blockIdx.y;
    const int nc = (q >> 3) + 1;
    const int tid = threadIdx.x;
    const int r  = tid >> 1;          // row 0..63
    const int dh = (tid & 1) * 32;    // col half

    const size_t base = (size_t)(b * NQT + q) * MAXC;
    float mc[MAXC], lc[MAXC];
    float mstar = -1e30f;
    for (int cgi = 0; cgi < nc; cgi++) {
        mc[cgi] = g_mpart[(base + cgi) * 64 + r];
        lc[cgi] = g_lpart[(base + cgi) * 64 + r];
        mstar = fmaxf(mstar, mc[cgi]);
    }
    float w[MAXC], lstar = 0.f;
    for (int cgi = 0; cgi < nc; cgi++) {
        w[cgi] = __expf(mc[cgi] - mstar);
        lstar += lc[cgi] * w[cgi];
    }
    const float inv = 1.0f / lstar;

    float* Ob = out + ((size_t)b * TSEQ + (size_t)q * 64 + r) * HEAD + dh;
#pragma unroll
    for (int j4 = 0; j4 < 8; j4++) {
        float4 acc = make_float4(0.f, 0.f, 0.f, 0.f);
        for (int cgi = 0; cgi < nc; cgi++) {
            const float* gp = g_opart + (base + cgi) * 4096 + r * 64 + dh + j4 * 4;
            float4 p = *(const float4*)gp;
            acc.x += w[cgi] * p.x; acc.y += w[cgi] * p.y;
            acc.z += w[cgi] * p.z; acc.w += w[cgi] * p.w;
        }
        *(float4*)&Ob[j4 * 4] =
            make_float4(acc.x * inv, acc.y * inv, acc.z * inv, acc.w * inv);
    }
}

// ---------------------------------------------------------------------------
extern "C" void kernel_launch(void* const* d_in, const int* in_sizes, int n_in,
                              void* d_out, int out_size)
{
    (void)in_sizes; (void)n_in; (void)out_size;
    const float* x  = (const float*)d_in[0];
    const float* Wq = (const float*)d_in[1];
    const float* Wk = (const float*)d_in[2];
    const float* Wv = (const float*)d_in[3];
    float* out = (float*)d_out;

    proj_kernel<<<(BATCH * TSEQ) / 64, 256>>>(x, Wq, Wk, Wv);

    const int smem_bytes = 4 * 64 * 64 * (int)sizeof(float);  // 64 KB
    cudaFuncSetAttribute(attn_kernel, cudaFuncAttributeMaxDynamicSharedMemorySize, smem_bytes);
    dim3 grid(UNITS_PER_B, BATCH);
    attn_kernel<<<grid, 128, smem_bytes>>>(out);

    dim3 cgrid(NQT - 8, BATCH);
    combine_kernel<<<cgrid, 128>>>(out);
}

// round 3
// speedup vs baseline: 3.7884x; 2.2387x over previous
#include <cuda_runtime.h>
#include <cuda_bf16.h>
#include <cstdint>

#define EMBED 384
#define HEAD  64
#define BATCH 4
#define TSEQ  4096
#define NQT   64
#define CHUNK 8
#define UNITS_PER_B 288
#define MAXC  8

// Scratch (__device__ globals per alloc rules).
__device__ float g_q[BATCH * TSEQ * HEAD];
__device__ float g_k[BATCH * TSEQ * HEAD];
__device__ float g_v[BATCH * TSEQ * HEAD];
__device__ float g_opart[BATCH * NQT * MAXC * 64 * 64];
__device__ float g_mpart[BATCH * NQT * MAXC * 64];
__device__ float g_lpart[BATCH * NQT * MAXC * 64];

// ---- tensor-core primitives -----------------------------------------------
__device__ __forceinline__ void ldsm4(uint32_t* r, uint32_t addr) {
    asm volatile("ldmatrix.sync.aligned.m8n8.x4.shared.b16 {%0,%1,%2,%3}, [%4];"
                 : "=r"(r[0]), "=r"(r[1]), "=r"(r[2]), "=r"(r[3]) : "r"(addr));
}
__device__ __forceinline__ void ldsm4t(uint32_t* r, uint32_t addr) {
    asm volatile("ldmatrix.sync.aligned.m8n8.x4.trans.shared.b16 {%0,%1,%2,%3}, [%4];"
                 : "=r"(r[0]), "=r"(r[1]), "=r"(r[2]), "=r"(r[3]) : "r"(addr));
}
__device__ __forceinline__ void mma16816(float* c, const uint32_t* a,
                                         uint32_t b0, uint32_t b1) {
    asm volatile(
        "mma.sync.aligned.m16n8k16.row.col.f32.bf16.bf16.f32 "
        "{%0,%1,%2,%3}, {%4,%5,%6,%7}, {%8,%9}, {%0,%1,%2,%3};"
        : "+f"(c[0]), "+f"(c[1]), "+f"(c[2]), "+f"(c[3])
        : "r"(a[0]), "r"(a[1]), "r"(a[2]), "r"(a[3]), "r"(b0), "r"(b1));
}
__device__ __forceinline__ uint32_t pack_bf16(__nv_bfloat16 a, __nv_bfloat16 b) {
    __nv_bfloat162 t = __halves2bfloat162(a, b);
    return *reinterpret_cast<uint32_t*>(&t);
}
// Split (x,y) into hi/lo bf16x2 pairs (x in low half = element 0).
__device__ __forceinline__ void split_pack(float x, float y, uint32_t& hi, uint32_t& lo) {
    __nv_bfloat16 hx = __float2bfloat16_rn(x);
    __nv_bfloat16 hy = __float2bfloat16_rn(y);
    hi = pack_bf16(hx, hy);
    __nv_bfloat16 lx = __float2bfloat16_rn(x - __bfloat162float(hx));
    __nv_bfloat16 ly = __float2bfloat16_rn(y - __bfloat162float(hy));
    lo = pack_bf16(lx, ly);
}

// Fill a 64x64 tile (row-major, ld=64) into swizzled bf16 hi/lo arrays.
// Swizzle: 16B chunk c of row r stored at chunk (c ^ (r&7)). 512 chunks total.
__device__ __forceinline__ void fill64(char* dh, char* dl, const float* src,
                                       float scale, int tid) {
#pragma unroll
    for (int it = 0; it < 4; it++) {
        int id = tid + it * 128;
        int r = id >> 3, c = id & 7;
        float4 f0 = *(const float4*)(src + r * 64 + c * 8);
        float4 f1 = *(const float4*)(src + r * 64 + c * 8 + 4);
        float v[8] = {f0.x * scale, f0.y * scale, f0.z * scale, f0.w * scale,
                      f1.x * scale, f1.y * scale, f1.z * scale, f1.w * scale};
        __nv_bfloat16 hb[8], lb[8];
#pragma unroll
        for (int j = 0; j < 8; j++) {
            hb[j] = __float2bfloat16_rn(v[j]);
            lb[j] = __float2bfloat16_rn(v[j] - __bfloat162float(hb[j]));
        }
        int off = r * 128 + ((c ^ (r & 7)) * 16);
        *(uint4*)(dh + off) = *(uint4*)hb;
        *(uint4*)(dl + off) = *(uint4*)lb;
    }
}

// ---------------------------------------------------------------------------
// Projection: y = x @ W, tensor-core bf16 3-split. Grid (256 row-tiles, 3 mats).
// 128 threads = 4 warps, each warp 16 rows x 64 cols.
// ---------------------------------------------------------------------------
#define PX_H 0
#define PX_L 5120
#define PW_H 10240
#define PW_L 14336
#define PROJ_SMEM 18432

__global__ __launch_bounds__(128) void proj_kernel(
    const float* __restrict__ x,
    const float* __restrict__ Wq,
    const float* __restrict__ Wk,
    const float* __restrict__ Wv)
{
    __shared__ char sm[PROJ_SMEM];
    uint32_t sbase = (uint32_t)__cvta_generic_to_shared(sm);

    const int tid  = threadIdx.x;
    const int lane = tid & 31;
    const int w    = tid >> 5;
    const int rw0  = w * 16;
    const int row0 = blockIdx.x * 64;
    const int mm   = blockIdx.y;
    const float* W = (mm == 0) ? Wq : ((mm == 1) ? Wk : Wv);
    float* g       = (mm == 0) ? g_q : ((mm == 1) ? g_k : g_v);

    float acc[8][4];
#pragma unroll
    for (int i = 0; i < 8; i++)
#pragma unroll
        for (int j = 0; j < 4; j++) acc[i][j] = 0.f;

    for (int k0 = 0; k0 < EMBED; k0 += 32) {
        __syncthreads();
        // X tile: 64 rows x 32 k, stride 40 bf16 (80B) -> (5r+c)%8 bank spread.
#pragma unroll
        for (int it = 0; it < 2; it++) {
            int id = tid + it * 128;           // 0..255
            int r = id >> 2, c = id & 3;
            const float* src = x + (size_t)(row0 + r) * EMBED + k0 + c * 8;
            float4 f0 = *(const float4*)src;
            float4 f1 = *(const float4*)(src + 4);
            float v[8] = {f0.x, f0.y, f0.z, f0.w, f1.x, f1.y, f1.z, f1.w};
            __nv_bfloat16 hb[8], lb[8];
#pragma unroll
            for (int j = 0; j < 8; j++) {
                hb[j] = __float2bfloat16_rn(v[j]);
                lb[j] = __float2bfloat16_rn(v[j] - __bfloat162float(hb[j]));
            }
            int off = r * 80 + c * 16;
            *(uint4*)(sm + PX_H + off) = *(uint4*)hb;
            *(uint4*)(sm + PX_L + off) = *(uint4*)lb;
        }
        // W tile: 32 k-rows x 64 n, stride 128B, XOR swizzle.
#pragma unroll
        for (int it = 0; it < 2; it++) {
            int id = tid + it * 128;
            int r = id >> 3, c = id & 7;       // r 0..31
            const float* src = W + (size_t)(k0 + r) * HEAD + c * 8;
            float4 f0 = *(const float4*)src;
            float4 f1 = *(const float4*)(src + 4);
            float v[8] = {f0.x, f0.y, f0.z, f0.w, f1.x, f1.y, f1.z, f1.w};
            __nv_bfloat16 hb[8], lb[8];
#pragma unroll
            for (int j = 0; j < 8; j++) {
                hb[j] = __float2bfloat16_rn(v[j]);
                lb[j] = __float2bfloat16_rn(v[j] - __bfloat162float(hb[j]));
            }
            int off = r * 128 + ((c ^ (r & 7)) * 16);
            *(uint4*)(sm + PW_H + off) = *(uint4*)hb;
            *(uint4*)(sm + PW_L + off) = *(uint4*)lb;
        }
        __syncthreads();

#pragma unroll
        for (int kk = 0; kk < 2; kk++) {
            uint32_t ah[4], al[4];
            int ra = rw0 + (lane & 15);
            uint32_t aoff = (uint32_t)(ra * 80 + (kk * 2 + (lane >> 4)) * 16);
            ldsm4(ah, sbase + PX_H + aoff);
            ldsm4(al, sbase + PX_L + aoff);
#pragma unroll
            for (int d2 = 0; d2 < 4; d2++) {
                int rb = kk * 16 + (lane & 7) + ((lane >> 3) & 1) * 8;
                uint32_t cb = (uint32_t)(d2 * 2 + (lane >> 4));
                uint32_t boff = (uint32_t)(rb * 128 + ((cb ^ (uint32_t)(rb & 7)) * 16));
                uint32_t bh[4], bl[4];
                ldsm4t(bh, sbase + PW_H + boff);
                ldsm4t(bl, sbase + PW_L + boff);
                mma16816(acc[2 * d2],     ah, bh[0], bh[1]);
                mma16816(acc[2 * d2],     ah, bl[0], bl[1]);
                mma16816(acc[2 * d2],     al, bh[0], bh[1]);
                mma16816(acc[2 * d2 + 1], ah, bh[2], bh[3]);
                mma16816(acc[2 * d2 + 1], ah, bl[2], bl[3]);
                mma16816(acc[2 * d2 + 1], al, bh[2], bh[3]);
            }
        }
    }

    const int rA = row0 + rw0 + (lane >> 2);
    const int rB = rA + 8;
#pragma unroll
    for (int nt = 0; nt < 8; nt++) {
        int cc = nt * 8 + 2 * (lane & 3);
        *(float2*)&g[(size_t)rA * HEAD + cc] = make_float2(acc[nt][0], acc[nt][1]);
        *(float2*)&g[(size_t)rB * HEAD + cc] = make_float2(acc[nt][2], acc[nt][3]);
    }
}

// ---------------------------------------------------------------------------
// Flash attention, split-KV, tensor-core bf16 3-split.
// 128 threads = 4 warps; warp w owns rows [w*16, w*16+16) of the 64-row q tile.
// ---------------------------------------------------------------------------
#define SA_QH 0
#define SA_QL 8192
#define SA_KH 16384
#define SA_KL 24576
#define SA_VH 32768
#define SA_VL 40960
#define ATTN_SMEM 49152

__global__ __launch_bounds__(128, 3) void attn_kernel(float* __restrict__ out)
{
    extern __shared__ char sm[];
    uint32_t sbase = (uint32_t)__cvta_generic_to_shared(sm);

    const int b   = blockIdx.y;
    const int uid = UNITS_PER_B - 1 - (int)blockIdx.x;  // heavy units first
    int rem = uid, band = 0;
    while (rem >= 8 * (band + 1)) { rem -= 8 * (band + 1); band++; }
    const int q  = band * 8 + rem / (band + 1);
    const int c  = rem % (band + 1);
    const int nc = (q >> 3) + 1;
    const int kt0 = c * CHUNK;
    const int kt1 = min(kt0 + CHUNK - 1, q);

    const int tid  = threadIdx.x;
    const int lane = tid & 31;
    const int w    = tid >> 5;
    const int rw0  = w * 16;

    const float* Qb = g_q + ((size_t)b * TSEQ + (size_t)q * 64) * HEAD;
    const float* Kb = g_k + (size_t)b * TSEQ * HEAD;
    const float* Vb = g_v + (size_t)b * TSEQ * HEAD;

    fill64(sm + SA_QH, sm + SA_QL, Qb, 0.125f, tid);   // scale folded into Q

    float O[8][4];
    float m2[2] = {-1e30f, -1e30f}, l2[2] = {0.f, 0.f};
#pragma unroll
    for (int i = 0; i < 8; i++)
#pragma unroll
        for (int j = 0; j < 4; j++) O[i][j] = 0.f;

    for (int kt = kt0; kt <= kt1; kt++) {
        __syncthreads();
        fill64(sm + SA_KH, sm + SA_KL, Kb + (size_t)kt * 64 * HEAD, 1.f, tid);
        fill64(sm + SA_VH, sm + SA_VL, Vb + (size_t)kt * 64 * HEAD, 1.f, tid);
        __syncthreads();

        // ---- S = Q @ K^T (3-pass bf16) ----
        float S[8][4];
#pragma unroll
        for (int i = 0; i < 8; i++)
#pragma unroll
            for (int j = 0; j < 4; j++) S[i][j] = 0.f;

#pragma unroll
        for (int kk = 0; kk < 4; kk++) {
            uint32_t ah[4], al[4];
            int ra = rw0 + (lane & 15);
            uint32_t ca = (uint32_t)(kk * 2 + (lane >> 4));
            uint32_t aoff = (uint32_t)(ra * 128 + ((ca ^ (uint32_t)(ra & 7)) * 16));
            ldsm4(ah, sbase + SA_QH + aoff);
            ldsm4(al, sbase + SA_QL + aoff);
#pragma unroll
            for (int n2 = 0; n2 < 4; n2++) {
                int rb = n2 * 16 + (lane & 7) + ((lane >> 4) ? 8 : 0);
                uint32_t cb = (uint32_t)(kk * 2 + ((lane >> 3) & 1));
                uint32_t boff = (uint32_t)(rb * 128 + ((cb ^ (uint32_t)(rb & 7)) * 16));
                uint32_t bh[4], bl[4];
                ldsm4(bh, sbase + SA_KH + boff);
                ldsm4(bl, sbase + SA_KL + boff);
                mma16816(S[2 * n2],     ah, bh[0], bh[1]);
                mma16816(S[2 * n2],     ah, bl[0], bl[1]);
                mma16816(S[2 * n2],     al, bh[0], bh[1]);
                mma16816(S[2 * n2 + 1], ah, bh[2], bh[3]);
                mma16816(S[2 * n2 + 1], ah, bl[2], bl[3]);
                mma16816(S[2 * n2 + 1], al, bh[2], bh[3]);
            }
        }

        if (kt == q) {  // diagonal tile: causal mask (local coords)
            int rl0 = rw0 + (lane >> 2);
            int cb  = 2 * (lane & 3);
#pragma unroll
            for (int nt = 0; nt < 8; nt++) {
#pragma unroll
                for (int j = 0; j < 4; j++) {
                    int col = nt * 8 + cb + (j & 1);
                    int row = rl0 + ((j >= 2) ? 8 : 0);
                    if (col > row) S[nt][j] = -1e30f;
                }
            }
        }

        // ---- online softmax (rows lane/4 and lane/4+8 of this warp) ----
#pragma unroll
        for (int h = 0; h < 2; h++) {
            float mx = -1e30f;
#pragma unroll
            for (int nt = 0; nt < 8; nt++)
                mx = fmaxf(mx, fmaxf(S[nt][2 * h], S[nt][2 * h + 1]));
            mx = fmaxf(mx, __shfl_xor_sync(0xffffffffu, mx, 1));
            mx = fmaxf(mx, __shfl_xor_sync(0xffffffffu, mx, 2));
            float mn    = fmaxf(m2[h], mx);
            float alpha = __expf(m2[h] - mn);
            float sum   = 0.f;
#pragma unroll
            for (int nt = 0; nt < 8; nt++) {
                float p0 = __expf(S[nt][2 * h]     - mn);
                float p1 = __expf(S[nt][2 * h + 1] - mn);
                S[nt][2 * h] = p0; S[nt][2 * h + 1] = p1;
                sum += p0 + p1;
            }
            sum += __shfl_xor_sync(0xffffffffu, sum, 1);
            sum += __shfl_xor_sync(0xffffffffu, sum, 2);
            l2[h] = l2[h] * alpha + sum;
            m2[h] = mn;
#pragma unroll
            for (int nt = 0; nt < 8; nt++) {
                O[nt][2 * h] *= alpha; O[nt][2 * h + 1] *= alpha;
            }
        }

        // ---- O += P @ V (3-pass bf16); P frags come straight from S regs ----
#pragma unroll
        for (int kk = 0; kk < 4; kk++) {
            uint32_t ph[4], pl[4];
            split_pack(S[2 * kk][0],     S[2 * kk][1],     ph[0], pl[0]);
            split_pack(S[2 * kk][2],     S[2 * kk][3],     ph[1], pl[1]);
            split_pack(S[2 * kk + 1][0], S[2 * kk + 1][1], ph[2], pl[2]);
            split_pack(S[2 * kk + 1][2], S[2 * kk + 1][3], ph[3], pl[3]);
#pragma unroll
            for (int d2 = 0; d2 < 4; d2++) {
                int rv = kk * 16 + (lane & 7) + ((lane >> 3) & 1) * 8;
                uint32_t cv = (uint32_t)(d2 * 2 + (lane >> 4));
                uint32_t voff = (uint32_t)(rv * 128 + ((cv ^ (uint32_t)(rv & 7)) * 16));
                uint32_t vh[4], vl[4];
                ldsm4t(vh, sbase + SA_VH + voff);
                ldsm4t(vl, sbase + SA_VL + voff);
                mma16816(O[2 * d2],     ph, vh[0], vh[1]);
                mma16816(O[2 * d2],     ph, vl[0], vl[1]);
                mma16816(O[2 * d2],     pl, vh[0], vh[1]);
                mma16816(O[2 * d2 + 1], ph, vh[2], vh[3]);
                mma16816(O[2 * d2 + 1], ph, vl[2], vl[3]);
                mma16816(O[2 * d2 + 1], pl, vh[2], vh[3]);
            }
        }
    }

    const int rA = rw0 + (lane >> 2);
    const int rB = rA + 8;
    if (nc == 1) {
        float* Ob = out + ((size_t)b * TSEQ + (size_t)q * 64) * HEAD;
        float i0 = 1.0f / l2[0], i1 = 1.0f / l2[1];
#pragma unroll
        for (int nt = 0; nt < 8; nt++) {
            int cc = nt * 8 + 2 * (lane & 3);
            *(float2*)&Ob[rA * HEAD + cc] = make_float2(O[nt][0] * i0, O[nt][1] * i0);
            *(float2*)&Ob[rB * HEAD + cc] = make_float2(O[nt][2] * i1, O[nt][3] * i1);
        }
    } else {
        float* gp = g_opart + (((size_t)(b * NQT + q) * MAXC + c) * 4096);
#pragma unroll
        for (int nt = 0; nt < 8; nt++) {
            int cc = nt * 8 + 2 * (lane & 3);
            *(float2*)&gp[rA * 64 + cc] = make_float2(O[nt][0], O[nt][1]);
            *(float2*)&gp[rB * 64 + cc] = make_float2(O[nt][2], O[nt][3]);
        }
        if ((lane & 3) == 0) {
            float* gm = g_mpart + ((size_t)(b * NQT + q) * MAXC + c) * 64;
            float* gl = g_lpart + ((size_t)(b * NQT + q) * MAXC + c) * 64;
            gm[rA] = m2[0]; gm[rB] = m2[1];
            gl[rA] = l2[0]; gl[rB] = l2[1];
        }
    }
}

// ---------------------------------------------------------------------------
// Combine split-KV partials (q tiles with nc >= 2).
// ---------------------------------------------------------------------------
__global__ __launch_bounds__(128) void combine_kernel(float* __restrict__ out)
{
    const int q  = 8 + blockIdx.x;
    const int b  = blockIdx.y;
    const int nc = (q >> 3) + 1;
    const int tid = threadIdx.x;
    const int r  = tid >> 1;
    const int dh = (tid & 1) * 32;

    const size_t base = (size_t)(b * NQT + q) * MAXC;
    float mc[MAXC], lc[MAXC];
    float mstar = -1e30f;
    for (int cgi = 0; cgi < nc; cgi++) {
        mc[cgi] = g_mpart[(base + cgi) * 64 + r];
        lc[cgi] = g_lpart[(base + cgi) * 64 + r];
        mstar = fmaxf(mstar, mc[cgi]);
    }
    float wgt[MAXC], lstar = 0.f;
    for (int cgi = 0; cgi < nc; cgi++) {
        wgt[cgi] = __expf(mc[cgi] - mstar);
        lstar += lc[cgi] * wgt[cgi];
    }
    const float inv = 1.0f / lstar;

    float* Ob = out + ((size_t)b * TSEQ + (size_t)q * 64 + r) * HEAD + dh;
#pragma unroll
    for (int j4 = 0; j4 < 8; j4++) {
        float4 acc = make_float4(0.f, 0.f, 0.f, 0.f);
        for (int cgi = 0; cgi < nc; cgi++) {
            const float* gp = g_opart + (base + cgi) * 4096 + r * 64 + dh + j4 * 4;
            float4 p = *(const float4*)gp;
            acc.x += wgt[cgi] * p.x; acc.y += wgt[cgi] * p.y;
            acc.z += wgt[cgi] * p.z; acc.w += wgt[cgi] * p.w;
        }
        *(float4*)&Ob[j4 * 4] =
            make_float4(acc.x * inv, acc.y * inv, acc.z * inv, acc.w * inv);
    }
}

// ---------------------------------------------------------------------------
extern "C" void kernel_launch(void* const* d_in, const int* in_sizes, int n_in,
                              void* d_out, int out_size)
{
    (void)in_sizes; (void)n_in; (void)out_size;
    const float* x  = (const float*)d_in[0];
    const float* Wq = (const float*)d_in[1];
    const float* Wk = (const float*)d_in[2];
    const float* Wv = (const float*)d_in[3];
    float* out = (float*)d_out;

    dim3 pgrid((BATCH * TSEQ) / 64, 3);
    proj_kernel<<<pgrid, 128>>>(x, Wq, Wk, Wv);

    cudaFuncSetAttribute(attn_kernel, cudaFuncAttributeMaxDynamicSharedMemorySize, ATTN_SMEM);
    dim3 grid(UNITS_PER_B, BATCH);
    attn_kernel<<<grid, 128, ATTN_SMEM>>>(out);

    dim3 cgrid(NQT - 8, BATCH);
    combine_kernel<<<cgrid, 128>>>(out);
}